// round 15
// baseline (speedup 1.0000x reference)
#include <cuda_runtime.h>

typedef unsigned long long u64;

// acc += 2.0 * {lo, hi}  (packed f32x2 FMA on the fma pipe)
__device__ __forceinline__ void fma2acc(u64& acc, float lo, float hi) {
    asm("{\n\t.reg .b64 t;\n\tmov.b64 t, {%1, %2};\n\tfma.rn.f32x2 %0, t, %3, %0;\n\t}"
        : "+l"(acc) : "f"(lo), "f"(hi), "l"(0x4000000040000000ull));
}
// acc += {lo, hi}  (packed f32x2 add on the fma pipe)
__device__ __forceinline__ void add2acc(u64& acc, float lo, float hi) {
    asm("{\n\t.reg .b64 t;\n\tmov.b64 t, {%1, %2};\n\tadd.rn.f32x2 %0, %0, t;\n\t}"
        : "+l"(acc) : "f"(lo), "f"(hi));
}

__device__ __forceinline__ void cp_async16(unsigned smem_addr, const void* gptr) {
    asm volatile("cp.async.cg.shared.global [%0], [%1], 16;" :: "r"(smem_addr), "l"(gptr));
}
__device__ __forceinline__ void cp_commit() {
    asm volatile("cp.async.commit_group;");
}
template<int N>
__device__ __forceinline__ void cp_wait() {
    asm volatile("cp.async.wait_group %0;" :: "n"(N));
}

// ---------------- scratch (device globals; no runtime allocation) ----------
__device__ float  g_patch[13565952];            // [K][M_pad] patches (3x3 layers)
__device__ float  g_bufA[16 * 256 * 38 * 38];   // act ping (pre-BN), 23.7 MB
__device__ float  g_bufB[16 * 512 * 19 * 19];   // act pong, 11.8 MB
__device__ float  g_wT[2000000];                // all-layer transposed weights
__device__ float  g_sumW[6][512];               // per-layer Sw[co]
__device__ double g_sum[6][512];
__device__ double g_sumsq[6][512];

__global__ void zero_stats_kernel() {
    int i = blockIdx.x * blockDim.x + threadIdx.x;
    if (i < 6 * 512) {
        (&g_sum[0][0])[i]   = 0.0;
        (&g_sumsq[0][0])[i] = 0.0;
        (&g_sumW[0][0])[i]  = 0.f;
    }
}

__device__ __forceinline__ float act6(float v, float sc, float sh) {
    return fminf(fmaxf(fmaf(v, sc, sh), 0.f), 6.f);
}

// BN fold for channel c from double sums (call sparingly — FP64).
__device__ __forceinline__ void bn_fold(const double* __restrict__ sum,
                                        const double* __restrict__ sumsq,
                                        const float* __restrict__ gamma,
                                        const float* __restrict__ beta,
                                        int c, int cnt, float& sc, float& sh)
{
    double mean = sum[c] / cnt;
    double var  = sumsq[c] / cnt - mean * mean;
    float rstd  = (float)(1.0 / sqrt(var + 1e-5));
    sc = gamma[c] * rstd;
    sh = beta[c] - (float)mean * sc;
}

// ---- 1x1 layers (L3/L5): NCHW -> [k][M_pad] transpose with BN fold --------
// One channel per block (blockIdx.y): thread 0 does the FP64 fold ONCE,
// broadcasts via smem.
__global__ void t1x1_kernel(const float* __restrict__ src, float* __restrict__ P,
                            const double* __restrict__ sum,
                            const double* __restrict__ sumsq,
                            const float* __restrict__ gamma,
                            const float* __restrict__ beta, int cnt,
                            int M, int M_pad, int HW, int Cin)
{
    __shared__ float2 fold;
    int k = blockIdx.y;
    if (threadIdx.x == 0) {
        float sc, sh;
        bn_fold(sum, sumsq, gamma, beta, k, cnt, sc, sh);
        fold = make_float2(sc, sh);
    }
    __syncthreads();
    int m0 = (blockIdx.x * blockDim.x + threadIdx.x) * 4;
    if (m0 >= M) return;
    float sc = fold.x, sh = fold.y;
    float4 v;
    float* vp = &v.x;
#pragma unroll
    for (int e = 0; e < 4; e++) {
        int m = m0 + e;
        int n = m / HW, s = m - n * HW;
        vp[e] = act6(src[((size_t)n * Cin + k) * HW + s], sc, sh);
    }
    *reinterpret_cast<float4*>(&P[(size_t)k * M_pad + m0]) = v;
}

// ---- 3x3 layers: im2col with BN fold (thread-0 fold); OOB->0 --------------
__global__ void im2col3x3_kernel(const float* __restrict__ src, float* __restrict__ P,
                                 const double* __restrict__ sum,
                                 const double* __restrict__ sumsq,
                                 const float* __restrict__ gamma,
                                 const float* __restrict__ beta, int cnt,
                                 int M, int M_pad, int Cin, int H, int W,
                                 int Ho, int Wo, int stride, int pad)
{
    __shared__ float2 fold;
    int k = blockIdx.y;
    int c  = k / 9;
    if (threadIdx.x == 0) {
        float sc, sh;
        bn_fold(sum, sumsq, gamma, beta, c, cnt, sc, sh);
        fold = make_float2(sc, sh);
    }
    __syncthreads();
    int m0 = (blockIdx.x * blockDim.x + threadIdx.x) * 4;
    if (m0 >= M) return;
    int r  = k - 9 * c;
    int ky = r / 3;
    int kx = r - 3 * ky;
    float sc = fold.x, sh = fold.y;
    int HoWo = Ho * Wo;
    float4 v;
    float* vp = &v.x;
#pragma unroll
    for (int e = 0; e < 4; e++) {
        int m  = m0 + e;
        int n  = m / HoWo, s  = m - n * HoWo;
        int oy = s / Wo,   ox = s - oy * Wo;
        int iy = oy * stride - pad + ky;
        int ix = ox * stride - pad + kx;
        float x = 0.f;
        if (iy >= 0 && iy < H && ix >= 0 && ix < W)
            x = act6(src[((size_t)(n * Cin + c) * H + iy) * W + ix], sc, sh);
        vp[e] = x;
    }
    *reinterpret_cast<float4*>(&P[(size_t)k * M_pad + m0]) = v;
}

// ---- batched weight transpose: ALL 6 layers in one launch ------------------
struct WtArgs {
    const float* w[6];
    float*       wT[6];
    float*       Sw[6];
    int K[6], Cout[6];
    int blkBase[7];
    int gx[6];
};

__global__ void wtrans_all_kernel(WtArgs a)
{
    __shared__ float t[32][33];
    int flat = blockIdx.x;
    int li = 0;
#pragma unroll
    for (int i = 0; i < 6; i++)
        if (flat >= a.blkBase[i + 1]) li = i + 1;
    int rel = flat - a.blkBase[li];
    int bx  = rel % a.gx[li];
    int by  = rel / a.gx[li];
    const float* w  = a.w[li];
    float* wT = a.wT[li];
    float* Sw = a.Sw[li];
    int K = a.K[li], Cout = a.Cout[li];
    int bk = bx * 32, bco = by * 32;
    int tx = threadIdx.x, ty = threadIdx.y;    // (32, 8)
#pragma unroll
    for (int i = 0; i < 4; i++) {
        int co = bco + ty + i * 8;
        t[ty + i * 8][tx] = w[(size_t)co * K + bk + tx];
    }
    __syncthreads();
#pragma unroll
    for (int i = 0; i < 4; i++) {
        int k = bk + ty + i * 8;
        wT[(size_t)k * Cout + bco + tx] = t[tx][ty + i * 8];
    }
    if (ty == 0) {
        float s = 0.f;
#pragma unroll
        for (int i = 0; i < 32; i++) s += t[tx][i];
        atomicAdd(&Sw[bco + tx], s);
    }
}

// ---------------------------------------------------------------------------
// Adder GEMM via min-identity:
//   pre[m,co] = 2*sum_k min(P[k,m],W[co,k]) - Sp[m] - Sw[co]
// DIRECT=1: P cp.async'd straight from NCHW source (per-image padded m).
// BNt: 64 (big layers) or 32 (small layers, 2x blocks).
// BK=32, cp.async double-buffered, Sp fused in-loop, BN stats fused.
// ---------------------------------------------------------------------------
template<int DIRECT, int BNt>
__global__ __launch_bounds__(128, 5)
void adder_gemm(const float* __restrict__ P, const float* __restrict__ Wt,
                const float* __restrict__ Sw,
                float* __restrict__ out,
                double* __restrict__ sum_g, double* __restrict__ sumsq_g,
                int M, int M_pad, int K, int Cout, int HoWo,
                int HWpad, int clamp_s)
{
    constexpr int BK = 32, BM = 64, TN = BNt / 8;
    constexpr int NT = 128;
    __shared__ float sP[2][BK][BM];
    __shared__ float sW[2][BK][BNt];

    const int tid = threadIdx.x;
    const int m0  = blockIdx.x * BM;
    const int n0  = blockIdx.y * BNt;
    const int txm = tid & 15;
    const int ty  = tid >> 4;
    const int tn0 = ty * TN;

    const int n_img = DIRECT ? (m0 / HWpad) : 0;
    const int s0    = DIRECT ? (m0 - n_img * HWpad) : 0;

    u64 acc[2][TN];
    u64 sp2[2] = {0ull, 0ull};
#pragma unroll
    for (int i = 0; i < 2; i++)
#pragma unroll
        for (int j = 0; j < TN; j++) acc[i][j] = 0ull;

    const float* gP = DIRECT ? (P + ((size_t)n_img * K) * HoWo)
                             : (P + m0);
    const float* gW = Wt + n0;
    const int nTiles = K / BK;

    auto issue_tile = [&](int t, int buf) {
        const float* bW = gW + (size_t)t * BK * Cout;
        if (DIRECT) {
            const float* bP = gP + (size_t)t * BK * HoWo;
#pragma unroll
            for (int r = 0; r < 4; r++) {
                int idx = r * NT + tid;
                int lk  = idx >> 4;
                int c4  = idx & 15;
                int s   = s0 + c4 * 4;
                if (s > clamp_s) s = clamp_s;
                cp_async16((unsigned)__cvta_generic_to_shared(&sP[buf][lk][c4 * 4]),
                           bP + (size_t)lk * HoWo + s);
            }
        } else {
            const float* bP = gP + (size_t)t * BK * M_pad;
#pragma unroll
            for (int r = 0; r < 4; r++) {
                int idx = r * NT + tid;
                int lk  = idx >> 4;
                int c4  = idx & 15;
                cp_async16((unsigned)__cvta_generic_to_shared(&sP[buf][lk][c4 * 4]),
                           bP + (size_t)lk * M_pad + c4 * 4);
            }
        }
        constexpr int WCH = BK * BNt / 4 / NT;
#pragma unroll
        for (int r = 0; r < WCH; r++) {
            int idx = r * NT + tid;
            int lk  = idx / (BNt / 4);
            int c4  = idx - lk * (BNt / 4);
            cp_async16((unsigned)__cvta_generic_to_shared(&sW[buf][lk][c4 * 4]),
                       bW + (size_t)lk * Cout + c4 * 4);
        }
        cp_commit();
    };

    issue_tile(0, 0);

    for (int t = 0; t < nTiles; t++) {
        int buf = t & 1;
        if (t + 1 < nTiles) {
            issue_tile(t + 1, buf ^ 1);
            cp_wait<1>();
        } else {
            cp_wait<0>();
        }
        __syncthreads();

#pragma unroll
        for (int kk = 0; kk < BK; kk++) {
            float4 p = *reinterpret_cast<const float4*>(&sP[buf][kk][txm * 4]);
            float wv[TN];
#pragma unroll
            for (int j4 = 0; j4 < TN / 4; j4++) {
                float4 w = *reinterpret_cast<const float4*>(&sW[buf][kk][tn0 + 4 * j4]);
                wv[4 * j4] = w.x; wv[4 * j4 + 1] = w.y;
                wv[4 * j4 + 2] = w.z; wv[4 * j4 + 3] = w.w;
            }
            add2acc(sp2[0], p.x, p.y);
            add2acc(sp2[1], p.z, p.w);
#pragma unroll
            for (int j = 0; j < TN; j++) {
                fma2acc(acc[0][j], fminf(p.x, wv[j]), fminf(p.y, wv[j]));
                fma2acc(acc[1][j], fminf(p.z, wv[j]), fminf(p.w, wv[j]));
            }
        }
        __syncthreads();
    }

    // ---- epilogue: val = acc(=2*sum min) - Sp[m] - Sw[co]; fused BN stats --
    float swA[TN];
#pragma unroll
    for (int j4 = 0; j4 < TN / 4; j4++) {
        float4 w = *reinterpret_cast<const float4*>(&Sw[n0 + tn0 + 4 * j4]);
        swA[4 * j4] = w.x; swA[4 * j4 + 1] = w.y;
        swA[4 * j4 + 2] = w.z; swA[4 * j4 + 3] = w.w;
    }
    float spL[4];
    spL[0] = __uint_as_float((unsigned int)(sp2[0] & 0xFFFFFFFFull));
    spL[1] = __uint_as_float((unsigned int)(sp2[0] >> 32));
    spL[2] = __uint_as_float((unsigned int)(sp2[1] & 0xFFFFFFFFull));
    spL[3] = __uint_as_float((unsigned int)(sp2[1] >> 32));

    float s_sum[TN], s_sq[TN];
#pragma unroll
    for (int j = 0; j < TN; j++) { s_sum[j] = 0.f; s_sq[j] = 0.f; }

#pragma unroll
    for (int i = 0; i < 2; i++) {
        bool okA, okB;
        int nA, sA, nB, sB;
        if (DIRECT) {
            sA = s0 + txm * 4 + 2 * i;
            sB = sA + 1;
            nA = nB = n_img;
            okA = sA < HoWo;
            okB = sB < HoWo;
        } else {
            int mA = m0 + txm * 4 + 2 * i;
            int mB = mA + 1;
            okA = mA < M; okB = mB < M;
            nA = okA ? mA / HoWo : 0; sA = mA - nA * HoWo;
            nB = okB ? mB / HoWo : 0; sB = mB - nB * HoWo;
        }
#pragma unroll
        for (int j = 0; j < TN; j++) {
            float lo = __uint_as_float((unsigned int)(acc[i][j] & 0xFFFFFFFFull));
            float hi = __uint_as_float((unsigned int)(acc[i][j] >> 32));
            float vA = lo - spL[2 * i]     - swA[j];
            float vB = hi - spL[2 * i + 1] - swA[j];
            int c = n0 + tn0 + j;
            if (okA) {
                out[(size_t)(nA * Cout + c) * HoWo + sA] = vA;
                s_sum[j] += vA; s_sq[j] += vA * vA;
            }
            if (okB) {
                out[(size_t)(nB * Cout + c) * HoWo + sB] = vB;
                s_sum[j] += vB; s_sq[j] += vB * vB;
            }
        }
    }
#pragma unroll
    for (int j = 0; j < TN; j++) {
        float a = s_sum[j], b = s_sq[j];
#pragma unroll
        for (int o = 1; o < 16; o <<= 1) {
            a += __shfl_xor_sync(0xffffffffu, a, o);
            b += __shfl_xor_sync(0xffffffffu, b, o);
        }
        if (txm == 0) {
            int c = n0 + tn0 + j;
            atomicAdd(&sum_g[c],   (double)a);
            atomicAdd(&sumsq_g[c], (double)b);
        }
    }
}

// Final BN + ReLU6 -> d_out, per-thread fold (only 4096 threads total).
__global__ void apply_bn_relu6(const float* __restrict__ pre,
                               float* __restrict__ out,
                               const double* __restrict__ sum,
                               const double* __restrict__ sumsq,
                               const float* __restrict__ gamma,
                               const float* __restrict__ beta, int cnt,
                               int total, int HoWo, int Cout)
{
    int i = blockIdx.x * blockDim.x + threadIdx.x;
    if (i < total) {
        int c = (i / HoWo) % Cout;
        float sc, sh;
        bn_fold(sum, sumsq, gamma, beta, c, cnt, sc, sh);
        out[i] = act6(pre[i], sc, sh);
    }
}

extern "C" void kernel_launch(void* const* d_in, const int* in_sizes, int n_in,
                              void* d_out, int out_size)
{
    (void)in_sizes; (void)n_in; (void)out_size;
    const float* x = (const float*)d_in[0];
    const float* W[6]; const float* G[6]; const float* B[6];
    for (int i = 0; i < 6; i++) {
        W[i] = (const float*)d_in[1 + 3 * i];
        G[i] = (const float*)d_in[2 + 3 * i];
        B[i] = (const float*)d_in[3 + 3 * i];
    }

    float *patch, *bufA, *bufB, *wT, *sw;
    double *sum, *sq;
    cudaGetSymbolAddress((void**)&patch, g_patch);
    cudaGetSymbolAddress((void**)&bufA,  g_bufA);
    cudaGetSymbolAddress((void**)&bufB,  g_bufB);
    cudaGetSymbolAddress((void**)&wT,    g_wT);
    cudaGetSymbolAddress((void**)&sw,    g_sumW);
    cudaGetSymbolAddress((void**)&sum,   g_sum);
    cudaGetSymbolAddress((void**)&sq,    g_sumsq);

    float  *SW6[6];
    double *SU[6], *SQ[6];
    for (int i = 0; i < 6; i++) {
        SW6[i] = sw + i * 512;
        SU[i] = sum + i * 512; SQ[i] = sq + i * 512;
    }

    const int Ks[6]    = {512, 2304, 512, 1152, 256, 1152};
    const int Couts[6] = {256, 512, 128, 256, 128, 256};
    float* WT[6];
    {
        size_t off = 0;
        for (int i = 0; i < 6; i++) { WT[i] = wT + off; off += (size_t)Ks[i] * Couts[i]; }
    }

    zero_stats_kernel<<<12, 256>>>();

    // One batched launch for all 6 weight transposes + column sums
    {
        WtArgs a;
        int base = 0;
        for (int i = 0; i < 6; i++) {
            a.w[i] = W[i]; a.wT[i] = WT[i]; a.Sw[i] = SW6[i];
            a.K[i] = Ks[i]; a.Cout[i] = Couts[i];
            a.gx[i] = Ks[i] / 32;
            a.blkBase[i] = base;
            base += (Ks[i] / 32) * (Couts[i] / 32);
        }
        a.blkBase[6] = base;
        wtrans_all_kernel<<<base, dim3(32, 8)>>>(a);
    }

    const size_t PAD = 8 * 1024;   // dummy dynamic smem -> 5 blocks/SM

    // ---------------- L1: 1x1 512->256 @38x38, DIRECT from x ----------------
    {
        const int K = 512, Cout = 256, HW = 1444, HWpad = 1472, Nimg = 16;
        const int M = Nimg * HW;
        adder_gemm<1, 64><<<dim3(Nimg * HWpad / 64, Cout / 64), 128, PAD>>>(
            x, WT[0], SW6[0], bufA, SU[0], SQ[0], M, 0, K, Cout, HW, HWpad, 1440);
    }
    // ---------------- L2: 3x3 256->512 s2p1 -> 19x19 ------------------------
    {
        const int M = 5776, M_pad = 5824, K = 2304, Cout = 512, HoWo = 361;
        im2col3x3_kernel<<<dim3((M / 4 + 255) / 256, K), 256>>>(
            bufA, patch, SU[0], SQ[0], G[0], B[0], 23104,
            M, M_pad, 256, 38, 38, 19, 19, 2, 1);
        adder_gemm<0, 64><<<dim3(M_pad / 64, Cout / 64), 128, PAD>>>(
            patch, WT[1], SW6[1], bufB, SU[1], SQ[1], M, M_pad, K, Cout, HoWo, 0, 0);
    }
    // ---------------- L3: 1x1 512->128 @19x19 -------------------------------
    {
        const int M = 5776, M_pad = 5824, K = 512, Cout = 128, HoWo = 361;
        t1x1_kernel<<<dim3((M / 4 + 255) / 256, K), 256>>>(
            bufB, patch, SU[1], SQ[1], G[1], B[1], 5776, M, M_pad, HoWo, K);
        adder_gemm<0, 32><<<dim3(M_pad / 64, Cout / 32), 128, PAD>>>(
            patch, WT[2], SW6[2], bufA, SU[2], SQ[2], M, M_pad, K, Cout, HoWo, 0, 0);
    }
    // ---------------- L4: 3x3 128->256 s2p1 -> 10x10 ------------------------
    {
        const int M = 1600, M_pad = 1600, K = 1152, Cout = 256, HoWo = 100;
        im2col3x3_kernel<<<dim3((M / 4 + 255) / 256, K), 256>>>(
            bufA, patch, SU[2], SQ[2], G[2], B[2], 5776,
            M, M_pad, 128, 19, 19, 10, 10, 2, 1);
        adder_gemm<0, 32><<<dim3(M_pad / 64, Cout / 32), 128, PAD>>>(
            patch, WT[3], SW6[3], bufB, SU[3], SQ[3], M, M_pad, K, Cout, HoWo, 0, 0);
    }
    // ---------------- L5: 1x1 256->128 @10x10 -------------------------------
    {
        const int M = 1600, M_pad = 1600, K = 256, Cout = 128, HoWo = 100;
        t1x1_kernel<<<dim3((M / 4 + 255) / 256, K), 256>>>(
            bufB, patch, SU[3], SQ[3], G[3], B[3], 1600, M, M_pad, HoWo, K);
        adder_gemm<0, 32><<<dim3(M_pad / 64, Cout / 32), 128, PAD>>>(
            patch, WT[4], SW6[4], bufA, SU[4], SQ[4], M, M_pad, K, Cout, HoWo, 0, 0);
    }
    // ---------------- L6: 3x3 128->256 s2p0 -> 4x4 --------------------------
    {
        const int M = 256, M_pad = 256, K = 1152, Cout = 256, HoWo = 16;
        im2col3x3_kernel<<<dim3(1, K), 256>>>(
            bufA, patch, SU[4], SQ[4], G[4], B[4], 1600,
            M, M_pad, 128, 10, 10, 4, 4, 2, 0);
        adder_gemm<0, 32><<<dim3(M_pad / 64, Cout / 32), 128, PAD>>>(
            patch, WT[5], SW6[5], bufB, SU[5], SQ[5], M, M_pad, K, Cout, HoWo, 0, 0);
    }

    // Final BN + ReLU6 -> d_out  [16, 256, 4, 4] (per-thread fold; tiny grid)
    int total = 16 * 256 * 4 * 4;
    apply_bn_relu6<<<(total + 255) / 256, 256>>>(bufB, (float*)d_out,
                                                 SU[5], SQ[5], G[5], B[5], 256,
                                                 total, 16, 256);
}

// round 17
// speedup vs baseline: 1.0350x; 1.0350x over previous
#include <cuda_runtime.h>

typedef unsigned long long u64;

// acc += 2.0 * {lo, hi}  (packed f32x2 FMA on the fma pipe)
__device__ __forceinline__ void fma2acc(u64& acc, float lo, float hi) {
    asm("{\n\t.reg .b64 t;\n\tmov.b64 t, {%1, %2};\n\tfma.rn.f32x2 %0, t, %3, %0;\n\t}"
        : "+l"(acc) : "f"(lo), "f"(hi), "l"(0x4000000040000000ull));
}
// acc += {lo, hi}  (packed f32x2 add on the fma pipe)
__device__ __forceinline__ void add2acc(u64& acc, float lo, float hi) {
    asm("{\n\t.reg .b64 t;\n\tmov.b64 t, {%1, %2};\n\tadd.rn.f32x2 %0, %0, t;\n\t}"
        : "+l"(acc) : "f"(lo), "f"(hi));
}

__device__ __forceinline__ void cp_async16(unsigned smem_addr, const void* gptr) {
    asm volatile("cp.async.cg.shared.global [%0], [%1], 16;" :: "r"(smem_addr), "l"(gptr));
}
__device__ __forceinline__ void cp_commit() {
    asm volatile("cp.async.commit_group;");
}
template<int N>
__device__ __forceinline__ void cp_wait() {
    asm volatile("cp.async.wait_group %0;" :: "n"(N));
}

// ---------------- scratch (device globals; no runtime allocation) ----------
__device__ float  g_patch[13565952];            // [K][M_pad] patches (3x3 layers)
__device__ float  g_bufA[16 * 256 * 38 * 38];   // act ping (pre-BN), 23.7 MB
__device__ float  g_bufB[16 * 512 * 19 * 19];   // act pong, 11.8 MB
__device__ float  g_wT[2000000];                // all-layer transposed weights
__device__ float  g_sumW[6][512];               // per-layer Sw[co]
__device__ double g_sum[6][512];
__device__ double g_sumsq[6][512];
__device__ float  g_scale[6][512];
__device__ float  g_shift[6][512];

__global__ void zero_stats_kernel() {
    int i = blockIdx.x * blockDim.x + threadIdx.x;
    if (i < 6 * 512) {
        (&g_sum[0][0])[i]   = 0.0;
        (&g_sumsq[0][0])[i] = 0.0;
        (&g_sumW[0][0])[i]  = 0.f;
    }
}

__device__ __forceinline__ float act6(float v, float sc, float sh) {
    return fminf(fmaxf(fmaf(v, sc, sh), 0.f), 6.f);
}

// ---- 1x1 layers (L3/L5): transpose with BN fold; HW compile-time ----------
template<int HW>
__global__ void t1x1_kernel(const float* __restrict__ src, float* __restrict__ P,
                            const float* __restrict__ scale,
                            const float* __restrict__ shift,
                            int M, int M_pad, int Cin)
{
    int k  = blockIdx.y;
    int m0 = (blockIdx.x * blockDim.x + threadIdx.x) * 4;
    if (m0 >= M) return;
    float sc = scale[k], sh = shift[k];
    float4 v;
    float* vp = &v.x;
#pragma unroll
    for (int e = 0; e < 4; e++) {
        int m = m0 + e;
        int n = m / HW, s = m - n * HW;          // const-div -> mul-shift
        vp[e] = act6(src[((size_t)n * Cin + k) * HW + s], sc, sh);
    }
    *reinterpret_cast<float4*>(&P[(size_t)k * M_pad + m0]) = v;
}

// ---- 3x3 layers: im2col with BN fold; ALL geometry compile-time -----------
template<int Cin, int H, int W, int Ho, int Wo, int STRIDE, int PAD>
__global__ void im2col3x3_kernel(const float* __restrict__ src, float* __restrict__ P,
                                 const float* __restrict__ scale,
                                 const float* __restrict__ shift,
                                 int M, int M_pad)
{
    constexpr int HoWo = Ho * Wo;
    int k  = blockIdx.y;
    int m0 = (blockIdx.x * blockDim.x + threadIdx.x) * 4;
    if (m0 >= M) return;
    int c  = k / 9;
    int r  = k - 9 * c;
    int ky = r / 3;
    int kx = r - 3 * ky;
    float sc = scale[c], sh = shift[c];
    float4 v;
    float* vp = &v.x;
#pragma unroll
    for (int e = 0; e < 4; e++) {
        int m  = m0 + e;
        int n  = m / HoWo, s  = m - n * HoWo;    // const-div
        int oy = s / Wo,   ox = s - oy * Wo;     // const-div
        int iy = oy * STRIDE - PAD + ky;
        int ix = ox * STRIDE - PAD + kx;
        float x = 0.f;
        if (iy >= 0 && iy < H && ix >= 0 && ix < W)
            x = act6(src[((size_t)(n * Cin + c) * H + iy) * W + ix], sc, sh);
        vp[e] = x;
    }
    *reinterpret_cast<float4*>(&P[(size_t)k * M_pad + m0]) = v;
}

// ---- batched weight transpose: ALL 6 layers in one launch ------------------
struct WtArgs {
    const float* w[6];
    float*       wT[6];
    float*       Sw[6];
    int K[6], Cout[6];
    int blkBase[7];
    int gx[6];
};

__global__ void wtrans_all_kernel(WtArgs a)
{
    __shared__ float t[32][33];
    int flat = blockIdx.x;
    int li = 0;
#pragma unroll
    for (int i = 0; i < 6; i++)
        if (flat >= a.blkBase[i + 1]) li = i + 1;
    int rel = flat - a.blkBase[li];
    int bx  = rel % a.gx[li];
    int by  = rel / a.gx[li];
    const float* w  = a.w[li];
    float* wT = a.wT[li];
    float* Sw = a.Sw[li];
    int K = a.K[li], Cout = a.Cout[li];
    int bk = bx * 32, bco = by * 32;
    int tx = threadIdx.x, ty = threadIdx.y;    // (32, 8)
#pragma unroll
    for (int i = 0; i < 4; i++) {
        int co = bco + ty + i * 8;
        t[ty + i * 8][tx] = w[(size_t)co * K + bk + tx];
    }
    __syncthreads();
#pragma unroll
    for (int i = 0; i < 4; i++) {
        int k = bk + ty + i * 8;
        wT[(size_t)k * Cout + bco + tx] = t[tx][ty + i * 8];
    }
    if (ty == 0) {
        float s = 0.f;
#pragma unroll
        for (int i = 0; i < 32; i++) s += t[tx][i];
        atomicAdd(&Sw[bco + tx], s);
    }
}

// ---------------------------------------------------------------------------
// Adder GEMM via min-identity:
//   pre[m,co] = 2*sum_k min(P[k,m],W[co,k]) - Sp[m] - Sw[co]
// DIRECT=1: P cp.async'd straight from NCHW source (per-image padded m).
// BNt: 64 (big layers) or 32 (small layers, 2x blocks).
// BK=32, cp.async double-buffered, Sp fused in-loop, BN stats fused.
// ---------------------------------------------------------------------------
template<int DIRECT, int BNt>
__global__ __launch_bounds__(128, 5)
void adder_gemm(const float* __restrict__ P, const float* __restrict__ Wt,
                const float* __restrict__ Sw,
                float* __restrict__ out,
                double* __restrict__ sum_g, double* __restrict__ sumsq_g,
                int M, int M_pad, int K, int Cout, int HoWo,
                int HWpad, int clamp_s)
{
    constexpr int BK = 32, BM = 64, TN = BNt / 8;
    constexpr int NT = 128;
    __shared__ float sP[2][BK][BM];
    __shared__ float sW[2][BK][BNt];

    const int tid = threadIdx.x;
    const int m0  = blockIdx.x * BM;
    const int n0  = blockIdx.y * BNt;
    const int txm = tid & 15;
    const int ty  = tid >> 4;
    const int tn0 = ty * TN;

    const int n_img = DIRECT ? (m0 / HWpad) : 0;
    const int s0    = DIRECT ? (m0 - n_img * HWpad) : 0;

    u64 acc[2][TN];
    u64 sp2[2] = {0ull, 0ull};
#pragma unroll
    for (int i = 0; i < 2; i++)
#pragma unroll
        for (int j = 0; j < TN; j++) acc[i][j] = 0ull;

    const float* gP = DIRECT ? (P + ((size_t)n_img * K) * HoWo)
                             : (P + m0);
    const float* gW = Wt + n0;
    const int nTiles = K / BK;

    auto issue_tile = [&](int t, int buf) {
        const float* bW = gW + (size_t)t * BK * Cout;
        if (DIRECT) {
            const float* bP = gP + (size_t)t * BK * HoWo;
#pragma unroll
            for (int r = 0; r < 4; r++) {
                int idx = r * NT + tid;
                int lk  = idx >> 4;
                int c4  = idx & 15;
                int s   = s0 + c4 * 4;
                if (s > clamp_s) s = clamp_s;
                cp_async16((unsigned)__cvta_generic_to_shared(&sP[buf][lk][c4 * 4]),
                           bP + (size_t)lk * HoWo + s);
            }
        } else {
            const float* bP = gP + (size_t)t * BK * M_pad;
#pragma unroll
            for (int r = 0; r < 4; r++) {
                int idx = r * NT + tid;
                int lk  = idx >> 4;
                int c4  = idx & 15;
                cp_async16((unsigned)__cvta_generic_to_shared(&sP[buf][lk][c4 * 4]),
                           bP + (size_t)lk * M_pad + c4 * 4);
            }
        }
        constexpr int WCH = BK * BNt / 4 / NT;
#pragma unroll
        for (int r = 0; r < WCH; r++) {
            int idx = r * NT + tid;
            int lk  = idx / (BNt / 4);
            int c4  = idx - lk * (BNt / 4);
            cp_async16((unsigned)__cvta_generic_to_shared(&sW[buf][lk][c4 * 4]),
                       bW + (size_t)lk * Cout + c4 * 4);
        }
        cp_commit();
    };

    issue_tile(0, 0);

    for (int t = 0; t < nTiles; t++) {
        int buf = t & 1;
        if (t + 1 < nTiles) {
            issue_tile(t + 1, buf ^ 1);
            cp_wait<1>();
        } else {
            cp_wait<0>();
        }
        __syncthreads();

#pragma unroll
        for (int kk = 0; kk < BK; kk++) {
            float4 p = *reinterpret_cast<const float4*>(&sP[buf][kk][txm * 4]);
            float wv[TN];
#pragma unroll
            for (int j4 = 0; j4 < TN / 4; j4++) {
                float4 w = *reinterpret_cast<const float4*>(&sW[buf][kk][tn0 + 4 * j4]);
                wv[4 * j4] = w.x; wv[4 * j4 + 1] = w.y;
                wv[4 * j4 + 2] = w.z; wv[4 * j4 + 3] = w.w;
            }
            add2acc(sp2[0], p.x, p.y);
            add2acc(sp2[1], p.z, p.w);
#pragma unroll
            for (int j = 0; j < TN; j++) {
                fma2acc(acc[0][j], fminf(p.x, wv[j]), fminf(p.y, wv[j]));
                fma2acc(acc[1][j], fminf(p.z, wv[j]), fminf(p.w, wv[j]));
            }
        }
        __syncthreads();
    }

    // ---- epilogue: val = acc(=2*sum min) - Sp[m] - Sw[co]; fused BN stats --
    float swA[TN];
#pragma unroll
    for (int j4 = 0; j4 < TN / 4; j4++) {
        float4 w = *reinterpret_cast<const float4*>(&Sw[n0 + tn0 + 4 * j4]);
        swA[4 * j4] = w.x; swA[4 * j4 + 1] = w.y;
        swA[4 * j4 + 2] = w.z; swA[4 * j4 + 3] = w.w;
    }
    float spL[4];
    spL[0] = __uint_as_float((unsigned int)(sp2[0] & 0xFFFFFFFFull));
    spL[1] = __uint_as_float((unsigned int)(sp2[0] >> 32));
    spL[2] = __uint_as_float((unsigned int)(sp2[1] & 0xFFFFFFFFull));
    spL[3] = __uint_as_float((unsigned int)(sp2[1] >> 32));

    float s_sum[TN], s_sq[TN];
#pragma unroll
    for (int j = 0; j < TN; j++) { s_sum[j] = 0.f; s_sq[j] = 0.f; }

#pragma unroll
    for (int i = 0; i < 2; i++) {
        bool okA, okB;
        int nA, sA, nB, sB;
        if (DIRECT) {
            sA = s0 + txm * 4 + 2 * i;
            sB = sA + 1;
            nA = nB = n_img;
            okA = sA < HoWo;
            okB = sB < HoWo;
        } else {
            int mA = m0 + txm * 4 + 2 * i;
            int mB = mA + 1;
            okA = mA < M; okB = mB < M;
            nA = okA ? mA / HoWo : 0; sA = mA - nA * HoWo;
            nB = okB ? mB / HoWo : 0; sB = mB - nB * HoWo;
        }
#pragma unroll
        for (int j = 0; j < TN; j++) {
            float lo = __uint_as_float((unsigned int)(acc[i][j] & 0xFFFFFFFFull));
            float hi = __uint_as_float((unsigned int)(acc[i][j] >> 32));
            float vA = lo - spL[2 * i]     - swA[j];
            float vB = hi - spL[2 * i + 1] - swA[j];
            int c = n0 + tn0 + j;
            if (okA) {
                out[(size_t)(nA * Cout + c) * HoWo + sA] = vA;
                s_sum[j] += vA; s_sq[j] += vA * vA;
            }
            if (okB) {
                out[(size_t)(nB * Cout + c) * HoWo + sB] = vB;
                s_sum[j] += vB; s_sq[j] += vB * vB;
            }
        }
    }
#pragma unroll
    for (int j = 0; j < TN; j++) {
        float a = s_sum[j], b = s_sq[j];
#pragma unroll
        for (int o = 1; o < 16; o <<= 1) {
            a += __shfl_xor_sync(0xffffffffu, a, o);
            b += __shfl_xor_sync(0xffffffffu, b, o);
        }
        if (txm == 0) {
            int c = n0 + tn0 + j;
            atomicAdd(&sum_g[c],   (double)a);
            atomicAdd(&sumsq_g[c], (double)b);
        }
    }
}

// Per-channel BN fold: double math exactly ONCE per channel.
__global__ void finalize_bn(const double* __restrict__ sum_g,
                            const double* __restrict__ sumsq_g,
                            const float* __restrict__ gamma,
                            const float* __restrict__ beta,
                            float* __restrict__ scale,
                            float* __restrict__ shift,
                            int Cout, int cnt)
{
    int c = blockIdx.x * blockDim.x + threadIdx.x;
    if (c < Cout) {
        double mean = sum_g[c] / cnt;
        double var  = sumsq_g[c] / cnt - mean * mean;
        float rstd  = (float)(1.0 / sqrt(var + 1e-5));
        float sc    = gamma[c] * rstd;
        scale[c]    = sc;
        shift[c]    = beta[c] - (float)mean * sc;
    }
}

__global__ void apply_bn_relu6(const float* __restrict__ pre,
                               float* __restrict__ out,
                               const float* __restrict__ scale,
                               const float* __restrict__ shift,
                               int total, int HoWo, int Cout)
{
    int i = blockIdx.x * blockDim.x + threadIdx.x;
    if (i < total) {
        int c = (i / HoWo) % Cout;
        out[i] = act6(pre[i], scale[c], shift[c]);
    }
}

extern "C" void kernel_launch(void* const* d_in, const int* in_sizes, int n_in,
                              void* d_out, int out_size)
{
    (void)in_sizes; (void)n_in; (void)out_size;
    const float* x = (const float*)d_in[0];
    const float* W[6]; const float* G[6]; const float* B[6];
    for (int i = 0; i < 6; i++) {
        W[i] = (const float*)d_in[1 + 3 * i];
        G[i] = (const float*)d_in[2 + 3 * i];
        B[i] = (const float*)d_in[3 + 3 * i];
    }

    float *patch, *bufA, *bufB, *wT, *sw, *scl, *shf;
    double *sum, *sq;
    cudaGetSymbolAddress((void**)&patch, g_patch);
    cudaGetSymbolAddress((void**)&bufA,  g_bufA);
    cudaGetSymbolAddress((void**)&bufB,  g_bufB);
    cudaGetSymbolAddress((void**)&wT,    g_wT);
    cudaGetSymbolAddress((void**)&sw,    g_sumW);
    cudaGetSymbolAddress((void**)&scl,   g_scale);
    cudaGetSymbolAddress((void**)&shf,   g_shift);
    cudaGetSymbolAddress((void**)&sum,   g_sum);
    cudaGetSymbolAddress((void**)&sq,    g_sumsq);

    float  *SW6[6], *SC[6], *SH[6];
    double *SU[6], *SQ[6];
    for (int i = 0; i < 6; i++) {
        SW6[i] = sw + i * 512; SC[i] = scl + i * 512; SH[i] = shf + i * 512;
        SU[i] = sum + i * 512; SQ[i] = sq + i * 512;
    }

    const int Ks[6]    = {512, 2304, 512, 1152, 256, 1152};
    const int Couts[6] = {256, 512, 128, 256, 128, 256};
    float* WT[6];
    {
        size_t off = 0;
        for (int i = 0; i < 6; i++) { WT[i] = wT + off; off += (size_t)Ks[i] * Couts[i]; }
    }

    zero_stats_kernel<<<12, 256>>>();

    // One batched launch for all 6 weight transposes + column sums
    {
        WtArgs a;
        int base = 0;
        for (int i = 0; i < 6; i++) {
            a.w[i] = W[i]; a.wT[i] = WT[i]; a.Sw[i] = SW6[i];
            a.K[i] = Ks[i]; a.Cout[i] = Couts[i];
            a.gx[i] = Ks[i] / 32;
            a.blkBase[i] = base;
            base += (Ks[i] / 32) * (Couts[i] / 32);
        }
        a.blkBase[6] = base;
        wtrans_all_kernel<<<base, dim3(32, 8)>>>(a);
    }

    const size_t PAD = 8 * 1024;   // dummy dynamic smem -> 5 blocks/SM

    // ---------------- L1: 1x1 512->256 @38x38, DIRECT from x ----------------
    {
        const int K = 512, Cout = 256, HW = 1444, HWpad = 1472, Nimg = 16;
        const int M = Nimg * HW;
        adder_gemm<1, 64><<<dim3(Nimg * HWpad / 64, Cout / 64), 128, PAD>>>(
            x, WT[0], SW6[0], bufA, SU[0], SQ[0], M, 0, K, Cout, HW, HWpad, 1440);
        finalize_bn<<<2, 128>>>(SU[0], SQ[0], G[0], B[0], SC[0], SH[0], Cout, M);
    }
    // ---------------- L2: 3x3 256->512 s2p1 -> 19x19 ------------------------
    {
        const int M = 5776, M_pad = 5824, K = 2304, Cout = 512, HoWo = 361;
        im2col3x3_kernel<256, 38, 38, 19, 19, 2, 1>
            <<<dim3((M / 4 + 255) / 256, K), 256>>>(bufA, patch, SC[0], SH[0], M, M_pad);
        adder_gemm<0, 64><<<dim3(M_pad / 64, Cout / 64), 128, PAD>>>(
            patch, WT[1], SW6[1], bufB, SU[1], SQ[1], M, M_pad, K, Cout, HoWo, 0, 0);
        finalize_bn<<<4, 128>>>(SU[1], SQ[1], G[1], B[1], SC[1], SH[1], Cout, M);
    }
    // ---------------- L3: 1x1 512->128 @19x19 -------------------------------
    {
        const int M = 5776, M_pad = 5824, K = 512, Cout = 128, HoWo = 361;
        t1x1_kernel<361><<<dim3((M / 4 + 255) / 256, K), 256>>>(
            bufB, patch, SC[1], SH[1], M, M_pad, K);
        adder_gemm<0, 32><<<dim3(M_pad / 64, Cout / 32), 128, PAD>>>(
            patch, WT[2], SW6[2], bufA, SU[2], SQ[2], M, M_pad, K, Cout, HoWo, 0, 0);
        finalize_bn<<<1, 128>>>(SU[2], SQ[2], G[2], B[2], SC[2], SH[2], Cout, M);
    }
    // ---------------- L4: 3x3 128->256 s2p1 -> 10x10 ------------------------
    {
        const int M = 1600, M_pad = 1600, K = 1152, Cout = 256, HoWo = 100;
        im2col3x3_kernel<128, 19, 19, 10, 10, 2, 1>
            <<<dim3((M / 4 + 255) / 256, K), 256>>>(bufA, patch, SC[2], SH[2], M, M_pad);
        adder_gemm<0, 32><<<dim3(M_pad / 64, Cout / 32), 128, PAD>>>(
            patch, WT[3], SW6[3], bufB, SU[3], SQ[3], M, M_pad, K, Cout, HoWo, 0, 0);
        finalize_bn<<<2, 128>>>(SU[3], SQ[3], G[3], B[3], SC[3], SH[3], Cout, M);
    }
    // ---------------- L5: 1x1 256->128 @10x10 -------------------------------
    {
        const int M = 1600, M_pad = 1600, K = 256, Cout = 128, HoWo = 100;
        t1x1_kernel<100><<<dim3((M / 4 + 255) / 256, K), 256>>>(
            bufB, patch, SC[3], SH[3], M, M_pad, K);
        adder_gemm<0, 32><<<dim3(M_pad / 64, Cout / 32), 128, PAD>>>(
            patch, WT[4], SW6[4], bufA, SU[4], SQ[4], M, M_pad, K, Cout, HoWo, 0, 0);
        finalize_bn<<<1, 128>>>(SU[4], SQ[4], G[4], B[4], SC[4], SH[4], Cout, M);
    }
    // ---------------- L6: 3x3 128->256 s2p0 -> 4x4 --------------------------
    {
        const int M = 256, M_pad = 256, K = 1152, Cout = 256, HoWo = 16;
        im2col3x3_kernel<128, 10, 10, 4, 4, 2, 0>
            <<<dim3(1, K), 256>>>(bufA, patch, SC[4], SH[4], M, M_pad);
        adder_gemm<0, 32><<<dim3(M_pad / 64, Cout / 32), 128, PAD>>>(
            patch, WT[5], SW6[5], bufB, SU[5], SQ[5], M, M_pad, K, Cout, HoWo, 0, 0);
        finalize_bn<<<2, 128>>>(SU[5], SQ[5], G[5], B[5], SC[5], SH[5], Cout, M);
    }

    // Final BN + ReLU6 -> d_out  [16, 256, 4, 4]
    int total = 16 * 256 * 4 * 4;
    apply_bn_relu6<<<(total + 255) / 256, 256>>>(bufB, (float*)d_out, SC[5], SH[5],
                                                 total, 16, 256);
}